// round 12
// baseline (speedup 1.0000x reference)
#include <cuda_runtime.h>
#include <math.h>

#define NRR 512
#define NAA 512
#define KC 4               // gaussian chunks per tile
#define NTILES 256         // 16x16 tiles of 32x32 px
#define NB 1024            // total blocks (16*16*4) -- one co-resident wave
#define MAXG 4096

// Scratch (device globals; no allocs). Zero-initialized at load.
__device__ float4 g_p0[MAXG];            // (rc, cc, A, B)
__device__ float4 g_p1[MAXG];            // (C, w, -, -)
__device__ float4 g_bb[MAXG];            // (rc, cc, er, ec)
__device__ float  g_part[KC][NRR*NAA];   // per-chunk partials (exclusive writes)
__device__ int    g_tick[NTILES];        // per-tile reduce tickets (self-reset)
__device__ int    g_ctr;                 // grid start-barrier counter
__device__ int    g_fin;                 // grid finish counter (resets g_ctr)

// One kernel, one wave: prep-once (grid-distributed) -> grid barrier ->
// cull -> splat -> partials -> per-tile ticket reduce.
__global__ __launch_bounds__(256, 8) void sar_kernel(
    const float* __restrict__ pos,
    const float* __restrict__ cov,
    const float* __restrict__ inten,
    float* __restrict__ out, int N)
{
    __shared__ int sIdx[256];
    __shared__ int warpTot[8];
    __shared__ int warpOff[8];
    __shared__ int sCount;
    __shared__ int sLast;

    const int tid  = threadIdx.x;
    const int lane = tid & 31;
    const int wid  = tid >> 5;
    const int tx   = tid & 31;
    const int ty   = tid >> 5;

    const int bx = blockIdx.x, by = blockIdx.y, bz = blockIdx.z;
    const int bid = (bz * 16 + by) * 16 + bx;      // 0..NB-1

    const float cbeta = 0.8660254037844387f;   // cos(30deg)
    const float sbeta = 0.5f;                  // sin(30deg)
    const float RCc   = 5773.502691896258f;    // ALT/cos(beta)
    const float RPY   = -2886.7513459481287f;  // radar pos y
    const float RPZ   = 5000.0f;
    const float L2E   = 1.4426950408889634f;

    // ---- phase 1: distributed prep, one gaussian per block (thread 0) ----
    if (tid == 0) {
        for (int n = bid; n < N; n += NB) {
            float dx = pos[n*3+0];
            float dy = pos[n*3+1] - RPY;
            float dz = pos[n*3+2] - RPZ;

            float Yr = -cbeta*dy - sbeta*dz;
            float Zr =  sbeta*dy - cbeta*dz;

            float Rmin = sqrtf(Yr*Yr + Zr*Zr + 1e-12f);
            float rc = Rmin + 256.0f - RCc;
            float cc = dx + 256.0f;
            float u1 = Yr / Rmin;
            float u2 = Zr / Rmin;

            const float* S = cov + n*9;
            float S00=S[0], S01=S[1], S02=S[2], S11=S[4], S12=S[5], S22=S[8];

            float c10 = -cbeta*S01 - sbeta*S02;
            float c20 =  sbeta*S01 - cbeta*S02;
            float c11 = cbeta*cbeta*S11 + 2.0f*cbeta*sbeta*S12 + sbeta*sbeta*S22;
            float c12 = cbeta*sbeta*(S22 - S11) + (cbeta*cbeta - sbeta*sbeta)*S12;
            float c22 = sbeta*sbeta*S11 - 2.0f*sbeta*cbeta*S12 + cbeta*cbeta*S22;

            float a  = u1*u1*c11 + 2.0f*u1*u2*c12 + u2*u2*c22 + 1e-4f;
            float b  = u1*c10 + u2*c20;
            float d2 = S00 + 1e-4f;

            float det = a*d2 - b*b;
            float inv = 1.0f / det;
            float A = -0.5f * L2E * d2 * inv;
            float B =         L2E * b  * inv;
            float C = -0.5f * L2E * a  * inv;
            float w = inten[n] * 0.15915494309189535f * inv;

            // mahal > 40: boundary terms <= exp(-20)*w ~ 2e-9 -> far below the
            // 1e-3 global tolerance (validated: rel_err pinned at 2.26e-7).
            const float T = 40.0f;
            float er = sqrtf(T * a);
            float ec = sqrtf(T * d2);

            g_p0[n] = make_float4(rc, cc, A, B);
            g_p1[n] = make_float4(C, w, 0.f, 0.f);
            g_bb[n] = make_float4(rc, cc, er, ec);
        }
        // ---- grid barrier (all NB blocks co-resident: one wave by design) ----
        __threadfence();                       // release preps
        atomicAdd(&g_ctr, 1);
        while (*((volatile int*)&g_ctr) < NB) { }
        __threadfence();                       // acquire others' preps
    }
    __syncthreads();

    const int chunk  = bz;
    const int tileId = by * 16 + bx;
    const int cbeg   = (chunk * N) / KC;
    const int cend   = ((chunk + 1) * N) / KC;

    const int   col  = bx * 32 + tx;
    const int   rowb = by * 32;
    const float colf = (float)col;
    const float rf0  = (float)(rowb + ty);
    const float r0   = (float)rowb;
    const float c0   = (float)(bx * 32);

    float acc0 = 0.f, acc1 = 0.f, acc2 = 0.f, acc3 = 0.f;

    for (int base = cbeg; base < cend; base += 256) {
        // ---- cull: one gaussian per thread (coalesced float4) ----
        const int n = base + tid;
        bool ok = false;
        if (n < cend) {
            float4 bb = g_bb[n];
            ok = (bb.x + bb.z >= r0) && (bb.x - bb.z <= r0 + 31.0f) &&
                 (bb.y + bb.w >= c0) && (bb.y - bb.w <= c0 + 31.0f);
        }
        unsigned bal = __ballot_sync(0xffffffffu, ok);
        if (lane == 0) warpTot[wid] = __popc(bal);
        __syncthreads();
        if (tid == 0) {
            int s = 0;
            #pragma unroll
            for (int w2 = 0; w2 < 8; w2++) { warpOff[w2] = s; s += warpTot[w2]; }
            sCount = s;
        }
        __syncthreads();
        if (ok) sIdx[warpOff[wid] + __popc(bal & ((1u << lane) - 1u))] = n;
        __syncthreads();

        // ---- splat survivors: 4 rows per thread ----
        const int M = sCount;
        #pragma unroll 2
        for (int i = 0; i < M; i++) {
            const int g = sIdx[i];
            const float4 p0 = g_p0[g];   // uniform -> LDG broadcast, L1 hit
            const float4 p1 = g_p1[g];

            float dc  = colf - p0.y;
            float Bdc = p0.w * dc;
            float Cq  = p1.x * dc * dc;
            float drb = rf0 - p0.x;

            float dr0 = drb;
            float dr1 = drb + 8.0f;
            float dr2 = drb + 16.0f;
            float dr3 = drb + 24.0f;

            float t0 = fmaf(p0.z, dr0, Bdc);
            float t1 = fmaf(p0.z, dr1, Bdc);
            float t2 = fmaf(p0.z, dr2, Bdc);
            float t3 = fmaf(p0.z, dr3, Bdc);

            float m0 = fmaf(t0, dr0, Cq);
            float m1 = fmaf(t1, dr1, Cq);
            float m2 = fmaf(t2, dr2, Cq);
            float m3 = fmaf(t3, dr3, Cq);

            float e0, e1, e2, e3;
            asm("ex2.approx.ftz.f32 %0, %1;" : "=f"(e0) : "f"(m0));
            asm("ex2.approx.ftz.f32 %0, %1;" : "=f"(e1) : "f"(m1));
            asm("ex2.approx.ftz.f32 %0, %1;" : "=f"(e2) : "f"(m2));
            asm("ex2.approx.ftz.f32 %0, %1;" : "=f"(e3) : "f"(m3));

            acc0 = fmaf(p1.y, e0, acc0);
            acc1 = fmaf(p1.y, e1, acc1);
            acc2 = fmaf(p1.y, e2, acc2);
            acc3 = fmaf(p1.y, e3, acc3);
        }
        __syncthreads();
    }

    // ---- write partial ----
    const int i0 = (rowb + ty      ) * NAA + col;
    const int i1 = (rowb + ty +  8 ) * NAA + col;
    const int i2 = (rowb + ty + 16 ) * NAA + col;
    const int i3 = (rowb + ty + 24 ) * NAA + col;
    float* dst = g_part[chunk];
    dst[i0] = acc0; dst[i1] = acc1; dst[i2] = acc2; dst[i3] = acc3;

    // ---- last chunk-block per tile reduces (fixed order -> deterministic) ----
    __threadfence();
    __syncthreads();
    if (tid == 0) {
        int old = atomicAdd(&g_tick[tileId], 1);
        sLast = (old == KC - 1) ? 1 : 0;
    }
    __syncthreads();
    if (sLast) {
        out[i0] = (g_part[0][i0] + g_part[1][i0]) + (g_part[2][i0] + g_part[3][i0]);
        out[i1] = (g_part[0][i1] + g_part[1][i1]) + (g_part[2][i1] + g_part[3][i1]);
        out[i2] = (g_part[0][i2] + g_part[1][i2]) + (g_part[2][i2] + g_part[3][i2]);
        out[i3] = (g_part[0][i3] + g_part[1][i3]) + (g_part[2][i3] + g_part[3][i3]);
        if (tid == 0) g_tick[tileId] = 0;   // self-reset for next replay
    }

    // ---- finish counter: overall-last block resets the start barrier ----
    if (tid == 0) {
        int f = atomicAdd(&g_fin, 1);
        if (f == NB - 1) { g_ctr = 0; g_fin = 0; __threadfence(); }
    }
}

extern "C" void kernel_launch(void* const* d_in, const int* in_sizes, int n_in,
                              void* d_out, int out_size)
{
    const float* pos   = (const float*)d_in[0];
    const float* cov   = (const float*)d_in[1];
    const float* inten = (const float*)d_in[2];
    float* out = (float*)d_out;

    int N = in_sizes[2];   // N_GAUSS
    if (N > MAXG) N = MAXG;

    dim3 grd(16, 16, KC);  // 1024 blocks = one co-resident wave at 8 blocks/SM
    sar_kernel<<<grd, 256>>>(pos, cov, inten, out, N);
}

// round 13
// speedup vs baseline: 1.5300x; 1.5300x over previous
#include <cuda_runtime.h>
#include <math.h>

#define NRR 512
#define NAA 512
#define KC 4               // gaussian chunks per tile (1024 blocks = one wave)
#define NTILES 256         // 16x16 tiles of 32x32 px

// Scratch (device globals; no allocs).
__device__ float g_part[KC][NRR * NAA];   // per-chunk partial images (exclusive writes)
__device__ int   g_tick[NTILES];          // per-tile completion tickets (self-resetting)

// Fused kernel, one pass per block (chunk size == 256 == blockDim):
// stage-1 cheap cull (pos + cov-trace bound) -> stage-2 full prep of loose
// survivors + exact cull -> splat -> partials -> per-tile ticket reduce.
__global__ __launch_bounds__(256) void sar_kernel(
    const float* __restrict__ pos,
    const float* __restrict__ cov,
    const float* __restrict__ inten,
    float* __restrict__ out, int N)
{
    __shared__ int    sIdx[256];      // loose-survivor gaussian ids
    __shared__ float4 sP0[256];       // (rc, cc, A, B)
    __shared__ float4 sP1[256];       // (C, w, -, -)
    __shared__ int    warpTot[8];
    __shared__ int    warpOff[8];
    __shared__ int    sMl;            // loose count
    __shared__ int    sCount;         // exact count
    __shared__ int    sLast;

    const int tid  = threadIdx.x;
    const int lane = tid & 31;
    const int wid  = tid >> 5;
    const int tx   = tid & 31;
    const int ty   = tid >> 5;

    const int chunk  = blockIdx.z;
    const int tileId = blockIdx.y * 16 + blockIdx.x;
    const int cbeg   = (chunk * N) / KC;
    const int cend   = ((chunk + 1) * N) / KC;

    const int   col  = blockIdx.x * 32 + tx;
    const int   rowb = blockIdx.y * 32;
    const float colf = (float)col;
    const float rf0  = (float)(rowb + ty);
    const float r0   = (float)rowb;
    const float c0   = (float)(blockIdx.x * 32);

    const float cbeta = 0.8660254037844387f;   // cos(30deg)
    const float sbeta = 0.5f;                  // sin(30deg)
    const float RCc   = 5773.502691896258f;    // ALT/cos(beta)
    const float RPY   = -2886.7513459481287f;  // radar pos y
    const float RPZ   = 5000.0f;
    const float L2E   = 1.4426950408889634f;
    const float T     = 40.0f;   // validated: rel_err pinned at 2.26e-7

    const unsigned lmask = (1u << lane) - 1u;

    float acc0 = 0.f, acc1 = 0.f, acc2 = 0.f, acc3 = 0.f;

    for (int base = cbeg; base < cend; base += 256) {
        // ---- stage 1: cheap cull (pos projection + trace bound) ----
        const int n = base + tid;
        bool okL = false;
        if (n < cend) {
            float dx = pos[n*3+0];
            float dy = pos[n*3+1] - RPY;
            float dz = pos[n*3+2] - RPZ;
            float Yr = -cbeta*dy - sbeta*dz;
            float Zr =  sbeta*dy - cbeta*dz;
            float Rmin = sqrtf(Yr*Yr + Zr*Zr + 1e-12f);
            float rc = Rmin + 256.0f - RCc;
            float cc = dx + 256.0f;
            // trace(cov)+1e-4 >= a and >= d2 for PSD cov -> bd >= er, ec
            float tr = cov[n*9+0] + cov[n*9+4] + cov[n*9+8] + 1e-4f;
            float bd = sqrtf(T * tr);
            okL = (rc + bd >= r0) && (rc - bd <= r0 + 31.0f) &&
                  (cc + bd >= c0) && (cc - bd <= c0 + 31.0f);
        }
        unsigned balL = __ballot_sync(0xffffffffu, okL);
        if (lane == 0) warpTot[wid] = __popc(balL);
        __syncthreads();
        if (tid == 0) {
            int s = 0;
            #pragma unroll
            for (int w2 = 0; w2 < 8; w2++) { warpOff[w2] = s; s += warpTot[w2]; }
            sMl = s;
        }
        __syncthreads();
        if (okL) sIdx[warpOff[wid] + __popc(balL & lmask)] = n;
        __syncthreads();

        // ---- stage 2: full prep of loose survivors only + exact cull ----
        const int Ml = sMl;
        bool  ok = false;
        float rc = 0.f, cc = 0.f, A = 0.f, B = 0.f, C = 0.f, w = 0.f;
        if (tid < Ml) {
            const int g = sIdx[tid];
            float dx = pos[g*3+0];
            float dy = pos[g*3+1] - RPY;
            float dz = pos[g*3+2] - RPZ;

            float Yr = -cbeta*dy - sbeta*dz;
            float Zr =  sbeta*dy - cbeta*dz;

            float Rmin = sqrtf(Yr*Yr + Zr*Zr + 1e-12f);
            rc = Rmin + 256.0f - RCc;
            cc = dx + 256.0f;
            float u1 = Yr / Rmin;
            float u2 = Zr / Rmin;

            const float* S = cov + g*9;
            float S00=S[0], S01=S[1], S02=S[2], S11=S[4], S12=S[5], S22=S[8];

            float c10 = -cbeta*S01 - sbeta*S02;
            float c20 =  sbeta*S01 - cbeta*S02;
            float c11 = cbeta*cbeta*S11 + 2.0f*cbeta*sbeta*S12 + sbeta*sbeta*S22;
            float c12 = cbeta*sbeta*(S22 - S11) + (cbeta*cbeta - sbeta*sbeta)*S12;
            float c22 = sbeta*sbeta*S11 - 2.0f*sbeta*cbeta*S12 + cbeta*cbeta*S22;

            float a  = u1*u1*c11 + 2.0f*u1*u2*c12 + u2*u2*c22 + 1e-4f;
            float b  = u1*c10 + u2*c20;
            float d2 = S00 + 1e-4f;

            float det = a*d2 - b*b;
            float inv = 1.0f / det;
            A = -0.5f * L2E * d2 * inv;
            B =         L2E * b  * inv;
            C = -0.5f * L2E * a  * inv;
            w = inten[g] * 0.15915494309189535f * inv;

            float er = sqrtf(T * a);
            float ec = sqrtf(T * d2);

            ok = (rc + er >= r0) && (rc - er <= r0 + 31.0f) &&
                 (cc + ec >= c0) && (cc - ec <= c0 + 31.0f);
        }

        unsigned bal = __ballot_sync(0xffffffffu, ok);
        if (lane == 0) warpTot[wid] = __popc(bal);
        __syncthreads();
        if (tid == 0) {
            int s = 0;
            #pragma unroll
            for (int w2 = 0; w2 < 8; w2++) { warpOff[w2] = s; s += warpTot[w2]; }
            sCount = s;
        }
        __syncthreads();
        if (ok) {
            int off = warpOff[wid] + __popc(bal & lmask);
            sP0[off] = make_float4(rc, cc, A, B);
            sP1[off] = make_float4(C, w, 0.f, 0.f);
        }
        __syncthreads();

        // ---- splat survivors: 4 rows per thread ----
        const int M = sCount;
        #pragma unroll 2
        for (int i = 0; i < M; i++) {
            const float4 p0 = sP0[i];   // uniform -> broadcast LDS
            const float4 p1 = sP1[i];

            float dc  = colf - p0.y;
            float Bdc = p0.w * dc;
            float Cq  = p1.x * dc * dc;
            float drb = rf0 - p0.x;

            float dr0 = drb;
            float dr1 = drb + 8.0f;
            float dr2 = drb + 16.0f;
            float dr3 = drb + 24.0f;

            float t0 = fmaf(p0.z, dr0, Bdc);
            float t1 = fmaf(p0.z, dr1, Bdc);
            float t2 = fmaf(p0.z, dr2, Bdc);
            float t3 = fmaf(p0.z, dr3, Bdc);

            float m0 = fmaf(t0, dr0, Cq);
            float m1 = fmaf(t1, dr1, Cq);
            float m2 = fmaf(t2, dr2, Cq);
            float m3 = fmaf(t3, dr3, Cq);

            float e0, e1, e2, e3;
            asm("ex2.approx.ftz.f32 %0, %1;" : "=f"(e0) : "f"(m0));
            asm("ex2.approx.ftz.f32 %0, %1;" : "=f"(e1) : "f"(m1));
            asm("ex2.approx.ftz.f32 %0, %1;" : "=f"(e2) : "f"(m2));
            asm("ex2.approx.ftz.f32 %0, %1;" : "=f"(e3) : "f"(m3));

            acc0 = fmaf(p1.y, e0, acc0);
            acc1 = fmaf(p1.y, e1, acc1);
            acc2 = fmaf(p1.y, e2, acc2);
            acc3 = fmaf(p1.y, e3, acc3);
        }
        __syncthreads();
    }

    // ---- write partial ----
    const int i0 = (rowb + ty      ) * NAA + col;
    const int i1 = (rowb + ty +  8 ) * NAA + col;
    const int i2 = (rowb + ty + 16 ) * NAA + col;
    const int i3 = (rowb + ty + 24 ) * NAA + col;
    float* dst = g_part[chunk];
    dst[i0] = acc0; dst[i1] = acc1; dst[i2] = acc2; dst[i3] = acc3;

    // ---- last block of this tile reduces (fixed chunk order -> deterministic) ----
    __threadfence();
    __syncthreads();
    if (tid == 0) {
        int old = atomicAdd(&g_tick[tileId], 1);
        sLast = (old == KC - 1) ? 1 : 0;
    }
    __syncthreads();
    if (sLast) {
        out[i0] = ((g_part[0][i0] + g_part[1][i0]) + (g_part[2][i0] + g_part[3][i0]));
        out[i1] = ((g_part[0][i1] + g_part[1][i1]) + (g_part[2][i1] + g_part[3][i1]));
        out[i2] = ((g_part[0][i2] + g_part[1][i2]) + (g_part[2][i2] + g_part[3][i2]));
        out[i3] = ((g_part[0][i3] + g_part[1][i3]) + (g_part[2][i3] + g_part[3][i3]));
        if (tid == 0) g_tick[tileId] = 0;   // self-reset for next graph replay
    }
}

extern "C" void kernel_launch(void* const* d_in, const int* in_sizes, int n_in,
                              void* d_out, int out_size)
{
    const float* pos   = (const float*)d_in[0];
    const float* cov   = (const float*)d_in[1];
    const float* inten = (const float*)d_in[2];
    float* out = (float*)d_out;

    int N = in_sizes[2];   // N_GAUSS

    dim3 grd(NAA / 32, NRR / 32, KC);
    sar_kernel<<<grd, 256>>>(pos, cov, inten, out, N);
}

// round 15
// speedup vs baseline: 1.7791x; 1.1628x over previous
#include <cuda_runtime.h>
#include <math.h>

#define NRR 512
#define NAA 512
#define KC 4               // gaussian chunks per tile (1024 blocks = one wave)
#define NTILES 256         // 16x16 tiles of 32x32 px

// Scratch (device globals; no allocs).
__device__ float g_part[KC][NRR * NAA];   // per-chunk partial images (exclusive writes)
__device__ int   g_tick[NTILES];          // per-tile completion tickets (self-resetting)

__device__ __forceinline__ float rsqrt_approx(float x) {
    float r; asm("rsqrt.approx.ftz.f32 %0, %1;" : "=f"(r) : "f"(x)); return r;
}
__device__ __forceinline__ float rcp_approx(float x) {
    float r; asm("rcp.approx.ftz.f32 %0, %1;" : "=f"(r) : "f"(x)); return r;
}
__device__ __forceinline__ float sqrt_approx(float x) {
    float r; asm("sqrt.approx.ftz.f32 %0, %1;" : "=f"(r) : "f"(x)); return r;
}
__device__ __forceinline__ float ex2_approx(float x) {
    float r; asm("ex2.approx.ftz.f32 %0, %1;" : "=f"(r) : "f"(x)); return r;
}

// Single fused kernel: prep + cull + splat + per-tile ticket reduce.
// Block = (tile x, tile y, chunk z). 256 threads: 32 cols x 8 row-groups, 4 rows/thread.
__global__ __launch_bounds__(256) void sar_kernel(
    const float* __restrict__ pos,
    const float* __restrict__ cov,
    const float* __restrict__ inten,
    float* __restrict__ out, int N)
{
    __shared__ float4   sP0[256];      // (rc, cc, A, B)
    __shared__ float4   sP1[256];      // (C, w, -, -)
    __shared__ unsigned sMask[8];
    __shared__ int      sLast;

    const int tid  = threadIdx.x;
    const int lane = tid & 31;
    const int wid  = tid >> 5;
    const int tx   = tid & 31;
    const int ty   = tid >> 5;

    const int chunk  = blockIdx.z;
    const int tileId = blockIdx.y * 16 + blockIdx.x;
    const int cbeg   = (chunk * N) / KC;
    const int cend   = ((chunk + 1) * N) / KC;

    const int   col  = blockIdx.x * 32 + tx;
    const int   rowb = blockIdx.y * 32;
    const float colf = (float)col;
    const float rf0  = (float)(rowb + ty);
    const float r0   = (float)rowb;
    const float c0   = (float)(blockIdx.x * 32);

    const float cbeta = 0.8660254037844387f;   // cos(30deg)
    const float sbeta = 0.5f;                  // sin(30deg)
    const float RPY   = -2886.7513459481287f;  // radar pos y
    const float RPZ   = 5000.0f;
    const float L2E   = 1.4426950408889634f;
    const float RCOFF = -5517.502691896258f;   // 256 - ALT/cos(beta)
    const float T     = 28.0f;   // boundary terms <= exp(-14)*w -> ~8e-7 rel, tol 1e-3

    const unsigned lmask = (1u << lane) - 1u;

    float acc0 = 0.f, acc1 = 0.f, acc2 = 0.f, acc3 = 0.f;

    for (int base = cbeg; base < cend; base += 256) {
        // ---- fused prep + cull: one gaussian per thread, in registers ----
        const int n = base + tid;
        bool  ok = false;
        float rc = 0.f, cc = 0.f, A = 0.f, B = 0.f, C = 0.f, w = 0.f;
        if (n < cend) {
            float dx = pos[n*3+0];
            float dy = pos[n*3+1] - RPY;
            float dz = pos[n*3+2] - RPZ;

            float Yr = -cbeta*dy - sbeta*dz;
            float Zr =  sbeta*dy - cbeta*dz;

            float q   = fmaf(Yr, Yr, fmaf(Zr, Zr, 1e-12f));
            float rrm = rsqrt_approx(q);        // 1/Rmin
            float Rmin = q * rrm;
            rc = Rmin + RCOFF;
            cc = dx + 256.0f;
            float u1 = Yr * rrm;
            float u2 = Zr * rrm;

            const float* S = cov + n*9;
            float S00=S[0], S01=S[1], S02=S[2], S11=S[4], S12=S[5], S22=S[8];

            float c10 = -cbeta*S01 - sbeta*S02;
            float c20 =  sbeta*S01 - cbeta*S02;
            float c11 = cbeta*cbeta*S11 + 2.0f*cbeta*sbeta*S12 + sbeta*sbeta*S22;
            float c12 = cbeta*sbeta*(S22 - S11) + (cbeta*cbeta - sbeta*sbeta)*S12;
            float c22 = sbeta*sbeta*S11 - 2.0f*sbeta*cbeta*S12 + cbeta*cbeta*S22;

            float a  = u1*u1*c11 + 2.0f*u1*u2*c12 + u2*u2*c22 + 1e-4f;
            float b  = u1*c10 + u2*c20;
            float d2 = S00 + 1e-4f;

            float det = fmaf(a, d2, -b*b);
            float inv = rcp_approx(det);
            A = -0.5f * L2E * d2 * inv;
            B =         L2E * b  * inv;
            C = -0.5f * L2E * a  * inv;
            w = inten[n] * 0.15915494309189535f * inv;

            float er = sqrt_approx(T * a);
            float ec = sqrt_approx(T * d2);

            ok = (rc + er >= r0) && (rc - er <= r0 + 31.0f) &&
                 (cc + ec >= c0) && (cc - ec <= c0 + 31.0f);
        }

        // ---- single-barrier deterministic compaction ----
        unsigned bal = __ballot_sync(0xffffffffu, ok);
        if (lane == 0) sMask[wid] = bal;
        __syncthreads();
        uint4 ma = *(const uint4*)&sMask[0];
        uint4 mb = *(const uint4*)&sMask[4];
        int cnt0 = __popc(ma.x), cnt1 = __popc(ma.y), cnt2 = __popc(ma.z), cnt3 = __popc(ma.w);
        int cnt4 = __popc(mb.x), cnt5 = __popc(mb.y), cnt6 = __popc(mb.z), cnt7 = __popc(mb.w);
        int off = __popc(bal & lmask);
        if (wid > 0) off += cnt0;
        if (wid > 1) off += cnt1;
        if (wid > 2) off += cnt2;
        if (wid > 3) off += cnt3;
        if (wid > 4) off += cnt4;
        if (wid > 5) off += cnt5;
        if (wid > 6) off += cnt6;
        const int M = ((cnt0 + cnt1) + (cnt2 + cnt3)) + ((cnt4 + cnt5) + (cnt6 + cnt7));
        if (ok) {
            sP0[off] = make_float4(rc, cc, A, B);
            sP1[off] = make_float4(C, w, 0.f, 0.f);
        }
        __syncthreads();

        // ---- splat survivors: 4 rows per thread ----
        #pragma unroll 2
        for (int i = 0; i < M; i++) {
            const float4 p0 = sP0[i];   // uniform -> broadcast LDS
            const float4 p1 = sP1[i];

            float dc  = colf - p0.y;
            float Bdc = p0.w * dc;
            float Cq  = p1.x * dc * dc;
            float drb = rf0 - p0.x;

            float dr0 = drb;
            float dr1 = drb + 8.0f;
            float dr2 = drb + 16.0f;
            float dr3 = drb + 24.0f;

            float t0 = fmaf(p0.z, dr0, Bdc);
            float t1 = fmaf(p0.z, dr1, Bdc);
            float t2 = fmaf(p0.z, dr2, Bdc);
            float t3 = fmaf(p0.z, dr3, Bdc);

            float e0 = ex2_approx(fmaf(t0, dr0, Cq));
            float e1 = ex2_approx(fmaf(t1, dr1, Cq));
            float e2 = ex2_approx(fmaf(t2, dr2, Cq));
            float e3 = ex2_approx(fmaf(t3, dr3, Cq));

            acc0 = fmaf(p1.y, e0, acc0);
            acc1 = fmaf(p1.y, e1, acc1);
            acc2 = fmaf(p1.y, e2, acc2);
            acc3 = fmaf(p1.y, e3, acc3);
        }
        __syncthreads();
    }

    // ---- write partial ----
    const int i0 = (rowb + ty      ) * NAA + col;
    const int i1 = (rowb + ty +  8 ) * NAA + col;
    const int i2 = (rowb + ty + 16 ) * NAA + col;
    const int i3 = (rowb + ty + 24 ) * NAA + col;
    float* dst = g_part[chunk];
    dst[i0] = acc0; dst[i1] = acc1; dst[i2] = acc2; dst[i3] = acc3;

    // ---- last block of this tile reduces (fixed chunk order -> deterministic:
    //      substituted register values are bitwise what was stored) ----
    __threadfence();
    __syncthreads();
    if (tid == 0) {
        int old = atomicAdd(&g_tick[tileId], 1);
        sLast = (old == KC - 1) ? 1 : 0;
    }
    __syncthreads();
    if (sLast) {
        {
            float p0v = (chunk == 0) ? acc0 : g_part[0][i0];
            float p1v = (chunk == 1) ? acc0 : g_part[1][i0];
            float p2v = (chunk == 2) ? acc0 : g_part[2][i0];
            float p3v = (chunk == 3) ? acc0 : g_part[3][i0];
            out[i0] = (p0v + p1v) + (p2v + p3v);
        }
        {
            float p0v = (chunk == 0) ? acc1 : g_part[0][i1];
            float p1v = (chunk == 1) ? acc1 : g_part[1][i1];
            float p2v = (chunk == 2) ? acc1 : g_part[2][i1];
            float p3v = (chunk == 3) ? acc1 : g_part[3][i1];
            out[i1] = (p0v + p1v) + (p2v + p3v);
        }
        {
            float p0v = (chunk == 0) ? acc2 : g_part[0][i2];
            float p1v = (chunk == 1) ? acc2 : g_part[1][i2];
            float p2v = (chunk == 2) ? acc2 : g_part[2][i2];
            float p3v = (chunk == 3) ? acc2 : g_part[3][i2];
            out[i2] = (p0v + p1v) + (p2v + p3v);
        }
        {
            float p0v = (chunk == 0) ? acc3 : g_part[0][i3];
            float p1v = (chunk == 1) ? acc3 : g_part[1][i3];
            float p2v = (chunk == 2) ? acc3 : g_part[2][i3];
            float p3v = (chunk == 3) ? acc3 : g_part[3][i3];
            out[i3] = (p0v + p1v) + (p2v + p3v);
        }
        if (tid == 0) g_tick[tileId] = 0;   // self-reset for next graph replay
    }
}

extern "C" void kernel_launch(void* const* d_in, const int* in_sizes, int n_in,
                              void* d_out, int out_size)
{
    const float* pos   = (const float*)d_in[0];
    const float* cov   = (const float*)d_in[1];
    const float* inten = (const float*)d_in[2];
    float* out = (float*)d_out;

    int N = in_sizes[2];   // N_GAUSS

    dim3 grd(NAA / 32, NRR / 32, KC);
    sar_kernel<<<grd, 256>>>(pos, cov, inten, out, N);
}

// round 16
// speedup vs baseline: 1.8214x; 1.0238x over previous
#include <cuda_runtime.h>
#include <math.h>

#define NRR 512
#define NAA 512
#define KC 4               // gaussian chunks per tile (1024 blocks = one wave)
#define NTILES 256         // 16x16 tiles of 32x32 px

// Scratch (device globals; no allocs).
__device__ float g_part[KC][NRR * NAA];   // per-chunk partial images (exclusive writes)
__device__ int   g_tick[NTILES];          // per-tile completion tickets (self-resetting)

__device__ __forceinline__ float rsqrt_approx(float x) {
    float r; asm("rsqrt.approx.ftz.f32 %0, %1;" : "=f"(r) : "f"(x)); return r;
}
__device__ __forceinline__ float rcp_approx(float x) {
    float r; asm("rcp.approx.ftz.f32 %0, %1;" : "=f"(r) : "f"(x)); return r;
}
__device__ __forceinline__ float sqrt_approx(float x) {
    float r; asm("sqrt.approx.ftz.f32 %0, %1;" : "=f"(r) : "f"(x)); return r;
}
__device__ __forceinline__ float ex2_approx(float x) {
    float r; asm("ex2.approx.ftz.f32 %0, %1;" : "=f"(r) : "f"(x)); return r;
}

// Single fused kernel: prep + cull + splat + per-tile ticket reduce.
// Block = (tile x, tile y, chunk z). 256 threads: 32 cols x 8 row-groups, 4 rows/thread.
__global__ __launch_bounds__(256, 8) void sar_kernel(
    const float* __restrict__ pos,
    const float* __restrict__ cov,
    const float* __restrict__ inten,
    float* __restrict__ out, int N)
{
    __shared__ float4   sP0[256];      // (rc, cc, A, B)
    __shared__ float4   sP1[256];      // (C, w, -, -)
    __shared__ unsigned sMask[8];
    __shared__ int      sLast;

    const int tid  = threadIdx.x;
    const int lane = tid & 31;
    const int wid  = tid >> 5;
    const int tx   = tid & 31;
    const int ty   = tid >> 5;

    const int chunk  = blockIdx.z;
    const int tileId = blockIdx.y * 16 + blockIdx.x;
    const int cbeg   = (chunk * N) / KC;
    const int cend   = ((chunk + 1) * N) / KC;

    const int   col  = blockIdx.x * 32 + tx;
    const int   rowb = blockIdx.y * 32;
    const float colf = (float)col;
    const float rf0  = (float)(rowb + ty);
    const float r0   = (float)rowb;
    const float c0   = (float)(blockIdx.x * 32);

    const float cbeta = 0.8660254037844387f;   // cos(30deg)
    const float sbeta = 0.5f;                  // sin(30deg)
    const float RPY   = -2886.7513459481287f;  // radar pos y
    const float RPZ   = 5000.0f;
    const float L2E   = 1.4426950408889634f;
    const float RCOFF = -5517.502691896258f;   // 256 - ALT/cos(beta)
    // Global rel_err ~= 173*exp(-T/2) (calibrated: T=28 -> 1.44e-4, T=40 -> noise
    // floor). T=32 -> ~2e-5, 50x inside the 1e-3 tolerance.
    const float T     = 32.0f;

    const unsigned lmask = (1u << lane) - 1u;

    float acc0 = 0.f, acc1 = 0.f, acc2 = 0.f, acc3 = 0.f;

    for (int base = cbeg; base < cend; base += 256) {
        if (base != cbeg) __syncthreads();   // smem reuse guard (no-op for N=1024)

        // ---- fused prep + cull: one gaussian per thread, in registers ----
        const int n = base + tid;
        bool  ok = false;
        float rc = 0.f, cc = 0.f, A = 0.f, B = 0.f, C = 0.f, w = 0.f;
        if (n < cend) {
            float dx = pos[n*3+0];
            float dy = pos[n*3+1] - RPY;
            float dz = pos[n*3+2] - RPZ;

            float Yr = -cbeta*dy - sbeta*dz;
            float Zr =  sbeta*dy - cbeta*dz;

            float q   = fmaf(Yr, Yr, fmaf(Zr, Zr, 1e-12f));
            float rrm = rsqrt_approx(q);        // 1/Rmin
            float Rmin = q * rrm;
            rc = Rmin + RCOFF;
            cc = dx + 256.0f;
            float u1 = Yr * rrm;
            float u2 = Zr * rrm;

            const float* S = cov + n*9;
            float S00=S[0], S01=S[1], S02=S[2], S11=S[4], S12=S[5], S22=S[8];

            float c10 = -cbeta*S01 - sbeta*S02;
            float c20 =  sbeta*S01 - cbeta*S02;
            float c11 = cbeta*cbeta*S11 + 2.0f*cbeta*sbeta*S12 + sbeta*sbeta*S22;
            float c12 = cbeta*sbeta*(S22 - S11) + (cbeta*cbeta - sbeta*sbeta)*S12;
            float c22 = sbeta*sbeta*S11 - 2.0f*sbeta*cbeta*S12 + cbeta*cbeta*S22;

            float a  = u1*u1*c11 + 2.0f*u1*u2*c12 + u2*u2*c22 + 1e-4f;
            float b  = u1*c10 + u2*c20;
            float d2 = S00 + 1e-4f;

            float det = fmaf(a, d2, -b*b);
            float inv = rcp_approx(det);
            A = -0.5f * L2E * d2 * inv;
            B =         L2E * b  * inv;
            C = -0.5f * L2E * a  * inv;
            w = inten[n] * 0.15915494309189535f * inv;

            float er = sqrt_approx(T * a);
            float ec = sqrt_approx(T * d2);

            ok = (rc + er >= r0) && (rc - er <= r0 + 31.0f) &&
                 (cc + ec >= c0) && (cc - ec <= c0 + 31.0f);
        }

        // ---- single-barrier deterministic compaction ----
        unsigned bal = __ballot_sync(0xffffffffu, ok);
        if (lane == 0) sMask[wid] = bal;
        __syncthreads();
        uint4 ma = *(const uint4*)&sMask[0];
        uint4 mb = *(const uint4*)&sMask[4];
        int cnt0 = __popc(ma.x), cnt1 = __popc(ma.y), cnt2 = __popc(ma.z), cnt3 = __popc(ma.w);
        int cnt4 = __popc(mb.x), cnt5 = __popc(mb.y), cnt6 = __popc(mb.z), cnt7 = __popc(mb.w);
        int off = __popc(bal & lmask);
        if (wid > 0) off += cnt0;
        if (wid > 1) off += cnt1;
        if (wid > 2) off += cnt2;
        if (wid > 3) off += cnt3;
        if (wid > 4) off += cnt4;
        if (wid > 5) off += cnt5;
        if (wid > 6) off += cnt6;
        const int M = ((cnt0 + cnt1) + (cnt2 + cnt3)) + ((cnt4 + cnt5) + (cnt6 + cnt7));
        if (ok) {
            sP0[off] = make_float4(rc, cc, A, B);
            sP1[off] = make_float4(C, w, 0.f, 0.f);
        }
        __syncthreads();

        // ---- splat survivors: 4 rows per thread ----
        #pragma unroll 2
        for (int i = 0; i < M; i++) {
            const float4 p0 = sP0[i];   // uniform -> broadcast LDS
            const float4 p1 = sP1[i];

            float dc  = colf - p0.y;
            float Bdc = p0.w * dc;
            float Cq  = p1.x * dc * dc;
            float drb = rf0 - p0.x;

            float dr0 = drb;
            float dr1 = drb + 8.0f;
            float dr2 = drb + 16.0f;
            float dr3 = drb + 24.0f;

            float t0 = fmaf(p0.z, dr0, Bdc);
            float t1 = fmaf(p0.z, dr1, Bdc);
            float t2 = fmaf(p0.z, dr2, Bdc);
            float t3 = fmaf(p0.z, dr3, Bdc);

            float e0 = ex2_approx(fmaf(t0, dr0, Cq));
            float e1 = ex2_approx(fmaf(t1, dr1, Cq));
            float e2 = ex2_approx(fmaf(t2, dr2, Cq));
            float e3 = ex2_approx(fmaf(t3, dr3, Cq));

            acc0 = fmaf(p1.y, e0, acc0);
            acc1 = fmaf(p1.y, e1, acc1);
            acc2 = fmaf(p1.y, e2, acc2);
            acc3 = fmaf(p1.y, e3, acc3);
        }
    }

    // ---- write partial ----
    const int i0 = (rowb + ty      ) * NAA + col;
    const int i1 = (rowb + ty +  8 ) * NAA + col;
    const int i2 = (rowb + ty + 16 ) * NAA + col;
    const int i3 = (rowb + ty + 24 ) * NAA + col;
    float* dst = g_part[chunk];
    dst[i0] = acc0; dst[i1] = acc1; dst[i2] = acc2; dst[i3] = acc3;

    // ---- last block of this tile reduces (fixed chunk order -> deterministic:
    //      substituted register values are bitwise what was stored) ----
    __threadfence();
    __syncthreads();
    if (tid == 0) {
        int old = atomicAdd(&g_tick[tileId], 1);
        sLast = (old == KC - 1) ? 1 : 0;
    }
    __syncthreads();
    if (sLast) {
        {
            float p0v = (chunk == 0) ? acc0 : g_part[0][i0];
            float p1v = (chunk == 1) ? acc0 : g_part[1][i0];
            float p2v = (chunk == 2) ? acc0 : g_part[2][i0];
            float p3v = (chunk == 3) ? acc0 : g_part[3][i0];
            out[i0] = (p0v + p1v) + (p2v + p3v);
        }
        {
            float p0v = (chunk == 0) ? acc1 : g_part[0][i1];
            float p1v = (chunk == 1) ? acc1 : g_part[1][i1];
            float p2v = (chunk == 2) ? acc1 : g_part[2][i1];
            float p3v = (chunk == 3) ? acc1 : g_part[3][i1];
            out[i1] = (p0v + p1v) + (p2v + p3v);
        }
        {
            float p0v = (chunk == 0) ? acc2 : g_part[0][i2];
            float p1v = (chunk == 1) ? acc2 : g_part[1][i2];
            float p2v = (chunk == 2) ? acc2 : g_part[2][i2];
            float p3v = (chunk == 3) ? acc2 : g_part[3][i2];
            out[i2] = (p0v + p1v) + (p2v + p3v);
        }
        {
            float p0v = (chunk == 0) ? acc3 : g_part[0][i3];
            float p1v = (chunk == 1) ? acc3 : g_part[1][i3];
            float p2v = (chunk == 2) ? acc3 : g_part[2][i3];
            float p3v = (chunk == 3) ? acc3 : g_part[3][i3];
            out[i3] = (p0v + p1v) + (p2v + p3v);
        }
        if (tid == 0) g_tick[tileId] = 0;   // self-reset for next graph replay
    }
}

extern "C" void kernel_launch(void* const* d_in, const int* in_sizes, int n_in,
                              void* d_out, int out_size)
{
    const float* pos   = (const float*)d_in[0];
    const float* cov   = (const float*)d_in[1];
    const float* inten = (const float*)d_in[2];
    float* out = (float*)d_out;

    int N = in_sizes[2];   // N_GAUSS

    dim3 grd(NAA / 32, NRR / 32, KC);
    sar_kernel<<<grd, 256>>>(pos, cov, inten, out, N);
}